// round 1
// baseline (speedup 1.0000x reference)
#include <cuda_runtime.h>
#include <math.h>

// Problem constants
#define BB 4
#define TT 1024
#define CC 1024
#define NH 16
#define HD 64
#define KKEEP 391
#define REC 64
#define NONREC (TT - REC)       // 960
// kept set = {960..1023} UNION top-327 of scores over t in [0,960)

// ---------------- scratch (device globals; no allocation allowed) ----------
__device__ float g_qkv[BB * TT * 3 * CC];   // 50.3 MB
__device__ float g_y[BB * TT * CC];         // 16.8 MB
__device__ float g_last[BB * NH * TT];
__device__ int   g_idx[BB * NH * KKEEP];

// ---------------- generic tiled SGEMM: C[M,N] = A[M,K] * B[K,N] ------------
// Row-major. Requires M%128==0, N%128==0, K%16==0 (true for both GEMMs here).
#define GBM 128
#define GBN 128
#define GBK 16
#define GTM 8
#define GTN 8

__global__ __launch_bounds__(256) void sgemm128(
    const float* __restrict__ A, const float* __restrict__ B,
    float* __restrict__ C, int M, int N, int K)
{
    __shared__ float As[GBK][GBM];
    __shared__ float Bs[GBK][GBN];

    const int tid = threadIdx.x;
    const int tx = tid % (GBN / GTN);   // 0..15
    const int ty = tid / (GBN / GTN);   // 0..15
    const int bx = blockIdx.x;          // N tile
    const int by = blockIdx.y;          // M tile

    const float* Ab = A + (size_t)by * GBM * K;
    const float* Bb = B + (size_t)bx * GBN;

    float acc[GTM][GTN];
    #pragma unroll
    for (int i = 0; i < GTM; i++)
        #pragma unroll
        for (int j = 0; j < GTN; j++) acc[i][j] = 0.f;

    for (int k0 = 0; k0 < K; k0 += GBK) {
        // Load A tile 128x16 (512 float4 -> 2 per thread), store transposed
        #pragma unroll
        for (int i = 0; i < 2; i++) {
            int idx = tid + i * 256;
            int r  = idx >> 2;          // 0..127
            int c4 = (idx & 3) * 4;     // 0,4,8,12
            float4 v = *(const float4*)(Ab + (size_t)r * K + k0 + c4);
            As[c4 + 0][r] = v.x; As[c4 + 1][r] = v.y;
            As[c4 + 2][r] = v.z; As[c4 + 3][r] = v.w;
        }
        // Load B tile 16x128 (512 float4 -> 2 per thread)
        #pragma unroll
        for (int i = 0; i < 2; i++) {
            int idx = tid + i * 256;
            int r  = idx >> 5;          // 0..15
            int c4 = (idx & 31) * 4;    // 0..124
            float4 v = *(const float4*)(Bb + (size_t)(k0 + r) * N + c4);
            *(float4*)&Bs[r][c4] = v;
        }
        __syncthreads();

        #pragma unroll
        for (int k = 0; k < GBK; k++) {
            float a[GTM], b[GTN];
            float4 a0 = *(float4*)&As[k][ty * GTM];
            float4 a1 = *(float4*)&As[k][ty * GTM + 4];
            a[0]=a0.x; a[1]=a0.y; a[2]=a0.z; a[3]=a0.w;
            a[4]=a1.x; a[5]=a1.y; a[6]=a1.z; a[7]=a1.w;
            float4 b0 = *(float4*)&Bs[k][tx * GTN];
            float4 b1 = *(float4*)&Bs[k][tx * GTN + 4];
            b[0]=b0.x; b[1]=b0.y; b[2]=b0.z; b[3]=b0.w;
            b[4]=b1.x; b[5]=b1.y; b[6]=b1.z; b[7]=b1.w;
            #pragma unroll
            for (int i = 0; i < GTM; i++)
                #pragma unroll
                for (int j = 0; j < GTN; j++)
                    acc[i][j] += a[i] * b[j];
        }
        __syncthreads();
    }

    float* Cb = C + (size_t)by * GBM * N + (size_t)bx * GBN;
    #pragma unroll
    for (int i = 0; i < GTM; i++) {
        #pragma unroll
        for (int j = 0; j < GTN; j += 4) {
            float4 v = make_float4(acc[i][j], acc[i][j+1], acc[i][j+2], acc[i][j+3]);
            *(float4*)(Cb + (size_t)(ty * GTM + i) * N + tx * GTN + j) = v;
        }
    }
}

// ---------------- last-row scores: last[b,h,t] = q[b,T-1,h,:]·k[b,t,h,:]/8 --
__global__ void last_scores_kernel(const float* __restrict__ qkv,
                                   float* __restrict__ last)
{
    int bh = blockIdx.x;            // 0..63
    int b = bh >> 4, h = bh & 15;
    __shared__ float qv[HD];
    const float* qrow = qkv + ((size_t)b * TT + (TT - 1)) * (3 * CC) + h * HD;
    if (threadIdx.x < HD) qv[threadIdx.x] = qrow[threadIdx.x];
    __syncthreads();
    for (int t = threadIdx.x; t < TT; t += blockDim.x) {
        const float* krow = qkv + ((size_t)b * TT + t) * (3 * CC) + CC + h * HD;
        float s = 0.f;
        #pragma unroll
        for (int d = 0; d < HD; d++) s += qv[d] * krow[d];
        last[bh * TT + t] = s * 0.125f;
    }
}

// ---------------- top-k set selection via bitonic sort ---------------------
// Recent positions (t>=960) keyed +inf -> always selected; set semantics make
// ordering irrelevant, so this matches the reference's recency+topk exactly.
__global__ __launch_bounds__(512) void topk_kernel(const float* __restrict__ last,
                                                   int* __restrict__ idxout)
{
    __shared__ unsigned long long s[TT];
    const int bh = blockIdx.x;
    const int tid = threadIdx.x;   // 512 threads

    for (int t = tid; t < TT; t += 512) {
        unsigned u;
        if (t >= NONREC) {
            u = 0xFFFFFFFFu;       // +inf key
        } else {
            u = __float_as_uint(last[bh * TT + t]);
            u = (u & 0x80000000u) ? ~u : (u | 0x80000000u);  // order-preserving flip
        }
        s[t] = ((unsigned long long)u << 32) | (unsigned)t;
    }
    __syncthreads();

    // bitonic sort, descending
    for (int k = 2; k <= TT; k <<= 1) {
        for (int j = k >> 1; j > 0; j >>= 1) {
            for (int i = tid; i < TT; i += 512) {
                int ix = i ^ j;
                if (ix > i) {
                    bool desc = ((i & k) == 0);
                    unsigned long long a = s[i], b = s[ix];
                    bool sw = desc ? (a < b) : (a > b);
                    if (sw) { s[i] = b; s[ix] = a; }
                }
            }
            __syncthreads();
        }
    }
    for (int i = tid; i < KKEEP; i += 512)
        idxout[bh * KKEEP + i] = (int)(s[i] & 0xFFFFFFFFu);
}

// ---------------- pruned attention ----------------------------------------
// One thread = one query row. K/V chunks of 64 keys staged in smem (gathered
// via idx). No max-subtraction: |score| < ~3 so exp is safe in fp32.
#define KCHUNK 64

__global__ __launch_bounds__(128) void attn_kernel(
    const float* __restrict__ qkv, const int* __restrict__ idx,
    float* __restrict__ y)
{
    const int bh = blockIdx.x;
    const int b = bh >> 4, h = bh & 15;
    const int qt = blockIdx.y * 128 + threadIdx.x;

    __shared__ float Ks[KCHUNK][HD];
    __shared__ float Vs[KCHUNK][HD];

    float q[HD];
    const float* qrow = qkv + ((size_t)b * TT + qt) * (3 * CC) + h * HD;
    #pragma unroll
    for (int d = 0; d < HD; d++) q[d] = qrow[d] * 0.125f;

    float l = 0.f;
    float acc[HD];
    #pragma unroll
    for (int d = 0; d < HD; d++) acc[d] = 0.f;

    for (int c0 = 0; c0 < KKEEP; c0 += KCHUNK) {
        const int cn = min(KCHUNK, KKEEP - c0);
        __syncthreads();
        // gather K and V rows for this chunk
        for (int i = threadIdx.x; i < cn * (HD / 4); i += 128) {
            int r = i >> 4;                  // key within chunk
            int c4 = (i & 15) * 4;           // float4 offset in head dim
            int kt = idx[bh * KKEEP + c0 + r];
            const float* kr = qkv + ((size_t)b * TT + kt) * (3 * CC) + CC + h * HD;
            *(float4*)&Ks[r][c4] = *(const float4*)(kr + c4);
            *(float4*)&Vs[r][c4] = *(const float4*)(kr + CC + c4);
        }
        __syncthreads();

        for (int kk = 0; kk < cn; kk++) {
            float sc = 0.f;
            #pragma unroll
            for (int d = 0; d < HD; d++) sc += q[d] * Ks[kk][d];
            float p = __expf(sc);
            l += p;
            #pragma unroll
            for (int d = 0; d < HD; d++) acc[d] += p * Vs[kk][d];
        }
    }

    float invl = 1.f / l;
    float* yrow = y + ((size_t)b * TT + qt) * CC + h * HD;
    #pragma unroll
    for (int d = 0; d < HD; d++) yrow[d] = acc[d] * invl;
}

// ---------------- launch ----------------------------------------------------
extern "C" void kernel_launch(void* const* d_in, const int* in_sizes, int n_in,
                              void* d_out, int out_size)
{
    const float* x  = (const float*)d_in[0];   // [4,1024,1024]
    const float* Wa = (const float*)d_in[1];   // [1024,3072]
    const float* Wp = (const float*)d_in[2];   // [1024,1024]
    float* out = (float*)d_out;                // [4,1024,1024]

    void* p;
    cudaGetSymbolAddress(&p, g_qkv);  float* qkv  = (float*)p;
    cudaGetSymbolAddress(&p, g_y);    float* y    = (float*)p;
    cudaGetSymbolAddress(&p, g_last); float* last = (float*)p;
    cudaGetSymbolAddress(&p, g_idx);  int*   idx  = (int*)p;

    // 1) qkv = x @ W_attn   [4096,1024]x[1024,3072]
    sgemm128<<<dim3(3 * CC / GBN, BB * TT / GBM), 256>>>(x, Wa, qkv, BB * TT, 3 * CC, CC);

    // 2) last-row scores
    last_scores_kernel<<<BB * NH, 256>>>(qkv, last);

    // 3) kept-index set per (b,h)
    topk_kernel<<<BB * NH, 512>>>(last, idx);

    // 4) pruned attention -> y [B,T,C]
    attn_kernel<<<dim3(BB * NH, TT / 128), 128>>>(qkv, idx, y);

    // 5) out = y @ W_proj   [4096,1024]x[1024,1024]
    sgemm128<<<dim3(CC / GBN, BB * TT / GBM), 256>>>(y, Wp, out, BB * TT, CC, CC);
}